// round 3
// baseline (speedup 1.0000x reference)
#include <cuda_runtime.h>

#define B 8
#define T 2048
#define D 1024
#define HS 64

typedef unsigned long long ull;

// ---- device scratch ----
__device__ float g_qT[B * HS * T];           // [b][c][t]
__device__ float g_kT[B * HS * T];           // [b][c][t]
__device__ float g_v [B * T * HS];           // [b][t][h]
__device__ float g_s [(size_t)B * T * T];    // [b][t][v] scores

// ---- packed f32x2 helpers (sm_103a FFMA2) ----
__device__ __forceinline__ ull splat2(float a) {
    ull r; asm("mov.b64 %0, {%1, %1};" : "=l"(r) : "f"(a)); return r;
}
__device__ __forceinline__ ull pack2(float x, float y) {
    ull r; asm("mov.b64 %0, {%1, %2};" : "=l"(r) : "f"(x), "f"(y)); return r;
}
__device__ __forceinline__ void ffma2(ull& d, ull a, ull b) {
    asm("fma.rn.f32x2 %0, %1, %2, %0;" : "+l"(d) : "l"(a), "l"(b));
}
__device__ __forceinline__ float2 unpack2(ull v) {
    float2 f; asm("mov.b64 {%0, %1}, %2;" : "=f"(f.x), "=f"(f.y) : "l"(v)); return f;
}

// =====================================================================
// K1: projections. BM=128 rows, 256 threads, microtile 8t x 4h, 3 mats.
// =====================================================================
__global__ __launch_bounds__(256) void proj_kernel(
    const float* __restrict__ x,
    const float* __restrict__ Wk, const float* __restrict__ bk,
    const float* __restrict__ Wq, const float* __restrict__ bq,
    const float* __restrict__ Wv, const float* __restrict__ bv)
{
    __shared__ float Xs[16 * 128];       // [c][t]
    __shared__ float Ws[3][16 * 64];     // [m][c][h]

    const int m0  = blockIdx.x * 128;
    const int tid = threadIdx.x;
    const int tg  = tid >> 4;
    const int hg  = tid & 15;

    const float* W[3] = {Wk, Wq, Wv};

    ull acc[3][8][2];
#pragma unroll
    for (int m = 0; m < 3; m++)
#pragma unroll
        for (int i = 0; i < 8; i++) { acc[m][i][0] = 0ull; acc[m][i][1] = 0ull; }

    for (int k0 = 0; k0 < D; k0 += 16) {
#pragma unroll
        for (int it = 0; it < 2; it++) {
            int idx = tid + it * 256;
            int r   = idx >> 2;
            int c4  = (idx & 3) << 2;
            float4 xv = *(const float4*)(x + (size_t)(m0 + r) * D + k0 + c4);
            Xs[(c4 + 0) * 128 + r] = xv.x; Xs[(c4 + 1) * 128 + r] = xv.y;
            Xs[(c4 + 2) * 128 + r] = xv.z; Xs[(c4 + 3) * 128 + r] = xv.w;
        }
#pragma unroll
        for (int m = 0; m < 3; m++) {
            int r  = tid >> 2;
            int c4 = (tid & 3) << 2;
            float4 wv = *(const float4*)(W[m] + (size_t)r * D + k0 + c4);
            Ws[m][(c4 + 0) * 64 + r] = wv.x; Ws[m][(c4 + 1) * 64 + r] = wv.y;
            Ws[m][(c4 + 2) * 64 + r] = wv.z; Ws[m][(c4 + 3) * 64 + r] = wv.w;
        }
        __syncthreads();

#pragma unroll
        for (int kk = 0; kk < 16; kk++) {
            float4 a0 = *(const float4*)&Xs[kk * 128 + tg * 8];
            float4 a1 = *(const float4*)&Xs[kk * 128 + tg * 8 + 4];
            ull as[8] = {splat2(a0.x), splat2(a0.y), splat2(a0.z), splat2(a0.w),
                         splat2(a1.x), splat2(a1.y), splat2(a1.z), splat2(a1.w)};
#pragma unroll
            for (int m = 0; m < 3; m++) {
                float4 w = *(const float4*)&Ws[m][kk * 64 + hg * 4];
                ull w0 = pack2(w.x, w.y), w1 = pack2(w.z, w.w);
#pragma unroll
                for (int i = 0; i < 8; i++) {
                    ffma2(acc[m][i][0], as[i], w0);
                    ffma2(acc[m][i][1], as[i], w1);
                }
            }
        }
        __syncthreads();
    }

    const float* bias[3] = {bk, bq, bv};
    const int b = m0 >> 11;
#pragma unroll
    for (int m = 0; m < 3; m++) {
        float4 bm = *(const float4*)(bias[m] + hg * 4);
        float bb[4] = {bm.x, bm.y, bm.z, bm.w};
#pragma unroll
        for (int i = 0; i < 8; i++) {
            int row = m0 + tg * 8 + i;
            int t   = row & (T - 1);
            float2 v0 = unpack2(acc[m][i][0]);
            float2 v1 = unpack2(acc[m][i][1]);
            float vals[4] = {v0.x + bb[0], v0.y + bb[1], v1.x + bb[2], v1.y + bb[3]};
            if (m == 0) {
#pragma unroll
                for (int j = 0; j < 4; j++)
                    g_kT[(size_t)(b * HS + hg * 4 + j) * T + t] = vals[j];
            } else if (m == 1) {
#pragma unroll
                for (int j = 0; j < 4; j++)
                    g_qT[(size_t)(b * HS + hg * 4 + j) * T + t] = vals[j];
            } else {
                *(float4*)(g_v + (size_t)row * HS + hg * 4) =
                    make_float4(vals[0], vals[1], vals[2], vals[3]);
            }
        }
    }
}

// =====================================================================
// K2a: S = 8 * q k^T.  BM=BN=128, 256 threads, microtile 8t x 8v.
// =====================================================================
__global__ __launch_bounds__(256) void qk_kernel()
{
    extern __shared__ float4 sm4[];
    float4* Q4 = sm4;             // [64][32]
    float4* K4 = sm4 + 64 * 32;   // [64][32]

    const int v0  = blockIdx.x * 128;
    const int t0  = blockIdx.y * 128;
    const int b   = blockIdx.z;
    const int tid = threadIdx.x;

    const float4* qT4 = (const float4*)g_qT;
    const float4* kT4 = (const float4*)g_kT;

#pragma unroll
    for (int it = 0; it < 8; it++) {
        int idx = tid + it * 256;
        int c = idx >> 5, x4 = idx & 31;
        Q4[idx] = qT4[(size_t)(b * HS + c) * (T / 4) + (t0 >> 2) + x4];
        K4[idx] = kT4[(size_t)(b * HS + c) * (T / 4) + (v0 >> 2) + x4];
    }
    __syncthreads();

    const int tg = tid >> 4;
    const int vg = tid & 15;

    ull acc[8][4];
#pragma unroll
    for (int i = 0; i < 8; i++)
#pragma unroll
        for (int p = 0; p < 4; p++) acc[i][p] = 0ull;

#pragma unroll 8
    for (int c = 0; c < 64; c++) {
        float4 a0 = Q4[c * 32 + tg * 2];
        float4 a1 = Q4[c * 32 + tg * 2 + 1];
        float4 k0 = K4[c * 32 + vg * 2];
        float4 k1 = K4[c * 32 + vg * 2 + 1];
        ull kp[4] = {pack2(k0.x, k0.y), pack2(k0.z, k0.w),
                     pack2(k1.x, k1.y), pack2(k1.z, k1.w)};
        ull as[8] = {splat2(a0.x), splat2(a0.y), splat2(a0.z), splat2(a0.w),
                     splat2(a1.x), splat2(a1.y), splat2(a1.z), splat2(a1.w)};
#pragma unroll
        for (int i = 0; i < 8; i++)
#pragma unroll
            for (int p = 0; p < 4; p++) ffma2(acc[i][p], as[i], kp[p]);
    }

#pragma unroll
    for (int i = 0; i < 8; i++) {
        int trow = t0 + tg * 8 + i;
        float* srow = g_s + ((size_t)(b * T + trow)) * T + v0 + vg * 8;
        float2 p0 = unpack2(acc[i][0]), p1 = unpack2(acc[i][1]);
        float2 p2 = unpack2(acc[i][2]), p3 = unpack2(acc[i][3]);
        *(float4*)(srow)     = make_float4(8.f * p0.x, 8.f * p0.y, 8.f * p1.x, 8.f * p1.y);
        *(float4*)(srow + 4) = make_float4(8.f * p2.x, 8.f * p2.y, 8.f * p3.x, 8.f * p3.y);
    }
}

// =====================================================================
// K2b: S += q . rel.  grid t. 512 threads = 128 v x 4 b-pairs.
// q pairs in registers (qp[64] = 128 regs, NO spill). rel read once.
// =====================================================================
__global__ __launch_bounds__(512) void rel_kernel(const float* __restrict__ rel)
{
    __shared__ float4 R4[128][16];   // 32 KB, XOR-swizzled
    __shared__ float  qs[8][64];     // 2 KB

    const int t   = blockIdx.x;
    const int tid = threadIdx.x;

    // stage q[8][64] for this t: one element per thread
    {
        int bb = tid >> 6, c = tid & 63;
        qs[bb][c] = g_qT[(size_t)(bb * HS + c) * T + t];
    }
    __syncthreads();

    const int v  = tid & 127;
    const int bp = tid >> 7;          // 0..3 -> batches 2bp, 2bp+1
    const int sw = v & 15;

    ull qp[64];
#pragma unroll
    for (int c = 0; c < 64; c++)
        qp[c] = pack2(qs[bp * 2 + 0][c], qs[bp * 2 + 1][c]);

    const float4* relt = (const float4*)(rel + (size_t)t * T * HS);
    const size_t TT = (size_t)T * T;
    const size_t srow = ((size_t)(bp * 2) * T + t) * T;

    for (int v0 = 0; v0 < T; v0 += 128) {
        __syncthreads();
#pragma unroll
        for (int it = 0; it < 4; it++) {
            int idx = tid + it * 512;     // 0..2047
            int vv  = idx >> 4;
            int c4  = idx & 15;
            R4[vv][c4 ^ (vv & 15)] = relt[(size_t)(v0 + vv) * 16 + c4];
        }
        __syncthreads();

        size_t si = srow + v0 + v;
        float s0 = g_s[si], s1 = g_s[si + TT];

        ull a = 0ull;
#pragma unroll
        for (int c4 = 0; c4 < 16; c4++) {
            float4 r4 = R4[v][c4 ^ sw];
            ffma2(a, qp[c4 * 4 + 0], splat2(r4.x));
            ffma2(a, qp[c4 * 4 + 1], splat2(r4.y));
            ffma2(a, qp[c4 * 4 + 2], splat2(r4.z));
            ffma2(a, qp[c4 * 4 + 3], splat2(r4.w));
        }
        float2 f = unpack2(a);
        g_s[si]      = s0 + f.x;
        g_s[si + TT] = s1 + f.y;
    }
}

// =====================================================================
// K3: softmax + PV. block = (16 t rows, b). 512 threads / 16 warps.
// warp w: softmax of row w; PV over 128-v slice. Partials in smem.
// =====================================================================
__global__ __launch_bounds__(512) void soft_pv_kernel(float* __restrict__ out)
{
    extern __shared__ float sm[];
    float* attT = sm;                       // [2048][17]  139.3 KB
    float* pout = sm + 2048 * 17;           // [16][16][64] 64 KB
    float* invl = pout + 16 * 16 * 64;      // [16]

    const int t0   = blockIdx.x * 16;
    const int b    = blockIdx.y;
    const int tid  = threadIdx.x;
    const int w    = tid >> 5;      // 0..15
    const int lane = tid & 31;

    // pass1: warp w -> row w max
    {
        const float4* srow4 = (const float4*)(g_s + ((size_t)(b * T + t0 + w)) * T);
        float m = -3.4e38f;
#pragma unroll
        for (int i = 0; i < 16; i++) {
            float4 sv = srow4[i * 32 + lane];
            m = fmaxf(m, fmaxf(fmaxf(sv.x, sv.y), fmaxf(sv.z, sv.w)));
        }
#pragma unroll
        for (int o = 16; o > 0; o >>= 1)
            m = fmaxf(m, __shfl_xor_sync(0xffffffffu, m, o));

        // pass2: exp, store transposed, sum
        const float* srow = g_s + ((size_t)(b * T + t0 + w)) * T;
        float sum = 0.f;
#pragma unroll 8
        for (int i = 0; i < 64; i++) {
            int vi = i * 32 + lane;
            float e = __expf(srow[vi] - m);
            attT[vi * 17 + w] = e;
            sum += e;
        }
#pragma unroll
        for (int o = 16; o > 0; o >>= 1)
            sum += __shfl_xor_sync(0xffffffffu, sum, o);
        if (lane == 0) invl[w] = 1.f / sum;
    }
    __syncthreads();

    // PV: warp w handles v in [w*128, w*128+128)
    const int th = lane >> 4;    // t-half: rows th*8..th*8+7
    const int hg = lane & 15;    // h = hg*4..hg*4+3
    const float4* vb = (const float4*)(g_v + (size_t)b * T * HS) + hg;

    ull acc[8][2];
#pragma unroll
    for (int j = 0; j < 8; j++) { acc[j][0] = 0ull; acc[j][1] = 0ull; }

    const int vbeg = w * 128;
#pragma unroll 2
    for (int v = vbeg; v < vbeg + 128; v++) {
        float4 vv = vb[(size_t)v * 16];
        ull vp0 = pack2(vv.x, vv.y), vp1 = pack2(vv.z, vv.w);
        const float* arow = attT + v * 17 + th * 8;
#pragma unroll
        for (int j = 0; j < 8; j++) {
            ull a = splat2(arow[j]);
            ffma2(acc[j][0], a, vp0);
            ffma2(acc[j][1], a, vp1);
        }
    }

    float* pw = pout + w * 1024;
#pragma unroll
    for (int j = 0; j < 8; j++) {
        int tt = th * 8 + j;
        float2 x0 = unpack2(acc[j][0]), x1 = unpack2(acc[j][1]);
        *(float4*)(pw + tt * 64 + hg * 4) = make_float4(x0.x, x0.y, x1.x, x1.y);
    }
    __syncthreads();

    // reduce 16 warps' partials: 512 threads x float2 = 1024 outputs
    {
        int tt = tid >> 5;            // 0..15
        int h2 = (tid & 31) * 2;      // 0..62 step 2
        float2 s = make_float2(0.f, 0.f);
#pragma unroll
        for (int ww = 0; ww < 16; ww++) {
            float2 p = *(float2*)(pout + ww * 1024 + tt * 64 + h2);
            s.x += p.x; s.y += p.y;
        }
        float sc = invl[tt];
        *(float2*)(out + ((size_t)(b * T + t0 + tt)) * HS + h2) =
            make_float2(s.x * sc, s.y * sc);
    }
}

// =====================================================================
extern "C" void kernel_launch(void* const* d_in, const int* in_sizes, int n_in,
                              void* d_out, int out_size)
{
    (void)in_sizes; (void)n_in; (void)out_size;
    const float* x   = (const float*)d_in[0];
    const float* Wk  = (const float*)d_in[1];
    const float* bk  = (const float*)d_in[2];
    const float* Wq  = (const float*)d_in[3];
    const float* bq  = (const float*)d_in[4];
    const float* Wv  = (const float*)d_in[5];
    const float* bv  = (const float*)d_in[6];
    const float* rel = (const float*)d_in[7];
    float* out = (float*)d_out;

    proj_kernel<<<(B * T) / 128, 256>>>(x, Wk, bk, Wq, bq, Wv, bv);

    const int qk_smem = 64 * 32 * 2 * sizeof(float4);   // 64 KB
    cudaFuncSetAttribute(qk_kernel, cudaFuncAttributeMaxDynamicSharedMemorySize, qk_smem);
    qk_kernel<<<dim3(T / 128, T / 128, B), 256, qk_smem>>>();

    rel_kernel<<<T, 512>>>(rel);

    const int k3_smem = (2048 * 17 + 16 * 16 * 64 + 16) * sizeof(float);  // ~200 KB
    cudaFuncSetAttribute(soft_pv_kernel, cudaFuncAttributeMaxDynamicSharedMemorySize, k3_smem);
    soft_pv_kernel<<<dim3(T / 16, B), 512, k3_smem>>>(out);
}

// round 4
// speedup vs baseline: 2.9078x; 2.9078x over previous
#include <cuda_runtime.h>
#include <cuda_fp16.h>

#define B 8
#define T 2048
#define D 1024
#define HS 64

typedef unsigned long long ull;

// ---- device scratch ----
__device__ float g_qT[B * HS * T];           // [b][c][t]
__device__ float g_kT[B * HS * T];           // [b][c][t]
__device__ float g_v [B * T * HS];           // [b][t][h]
__device__ float g_s [(size_t)B * T * T];    // [b][t][v] scores

// ---- packed f32x2 helpers (sm_103a FFMA2) ----
__device__ __forceinline__ ull splat2(float a) {
    ull r; asm("mov.b64 %0, {%1, %1};" : "=l"(r) : "f"(a)); return r;
}
__device__ __forceinline__ ull pack2(float x, float y) {
    ull r; asm("mov.b64 %0, {%1, %2};" : "=l"(r) : "f"(x), "f"(y)); return r;
}
__device__ __forceinline__ void ffma2(ull& d, ull a, ull b) {
    asm("fma.rn.f32x2 %0, %1, %2, %0;" : "+l"(d) : "l"(a), "l"(b));
}
__device__ __forceinline__ float2 unpack2(ull v) {
    float2 f; asm("mov.b64 {%0, %1}, %2;" : "=f"(f.x), "=f"(f.y) : "l"(v)); return f;
}

// =====================================================================
// K1: projections. BM=128 rows, 256 threads, microtile 8t x 4h, 3 mats.
// =====================================================================
__global__ __launch_bounds__(256) void proj_kernel(
    const float* __restrict__ x,
    const float* __restrict__ Wk, const float* __restrict__ bk,
    const float* __restrict__ Wq, const float* __restrict__ bq,
    const float* __restrict__ Wv, const float* __restrict__ bv)
{
    __shared__ float Xs[16 * 128];       // [c][t]
    __shared__ float Ws[3][16 * 64];     // [m][c][h]

    const int m0  = blockIdx.x * 128;
    const int tid = threadIdx.x;
    const int tg  = tid >> 4;
    const int hg  = tid & 15;

    const float* W[3] = {Wk, Wq, Wv};

    ull acc[3][8][2];
#pragma unroll
    for (int m = 0; m < 3; m++)
#pragma unroll
        for (int i = 0; i < 8; i++) { acc[m][i][0] = 0ull; acc[m][i][1] = 0ull; }

    for (int k0 = 0; k0 < D; k0 += 16) {
#pragma unroll
        for (int it = 0; it < 2; it++) {
            int idx = tid + it * 256;
            int r   = idx >> 2;
            int c4  = (idx & 3) << 2;
            float4 xv = *(const float4*)(x + (size_t)(m0 + r) * D + k0 + c4);
            Xs[(c4 + 0) * 128 + r] = xv.x; Xs[(c4 + 1) * 128 + r] = xv.y;
            Xs[(c4 + 2) * 128 + r] = xv.z; Xs[(c4 + 3) * 128 + r] = xv.w;
        }
#pragma unroll
        for (int m = 0; m < 3; m++) {
            int r  = tid >> 2;
            int c4 = (tid & 3) << 2;
            float4 wv = *(const float4*)(W[m] + (size_t)r * D + k0 + c4);
            Ws[m][(c4 + 0) * 64 + r] = wv.x; Ws[m][(c4 + 1) * 64 + r] = wv.y;
            Ws[m][(c4 + 2) * 64 + r] = wv.z; Ws[m][(c4 + 3) * 64 + r] = wv.w;
        }
        __syncthreads();

#pragma unroll
        for (int kk = 0; kk < 16; kk++) {
            float4 a0 = *(const float4*)&Xs[kk * 128 + tg * 8];
            float4 a1 = *(const float4*)&Xs[kk * 128 + tg * 8 + 4];
            ull as[8] = {splat2(a0.x), splat2(a0.y), splat2(a0.z), splat2(a0.w),
                         splat2(a1.x), splat2(a1.y), splat2(a1.z), splat2(a1.w)};
#pragma unroll
            for (int m = 0; m < 3; m++) {
                float4 w = *(const float4*)&Ws[m][kk * 64 + hg * 4];
                ull w0 = pack2(w.x, w.y), w1 = pack2(w.z, w.w);
#pragma unroll
                for (int i = 0; i < 8; i++) {
                    ffma2(acc[m][i][0], as[i], w0);
                    ffma2(acc[m][i][1], as[i], w1);
                }
            }
        }
        __syncthreads();
    }

    const float* bias[3] = {bk, bq, bv};
    const int b = m0 >> 11;
#pragma unroll
    for (int m = 0; m < 3; m++) {
        float4 bm = *(const float4*)(bias[m] + hg * 4);
        float bb[4] = {bm.x, bm.y, bm.z, bm.w};
#pragma unroll
        for (int i = 0; i < 8; i++) {
            int row = m0 + tg * 8 + i;
            int t   = row & (T - 1);
            float2 v0 = unpack2(acc[m][i][0]);
            float2 v1 = unpack2(acc[m][i][1]);
            float vals[4] = {v0.x + bb[0], v0.y + bb[1], v1.x + bb[2], v1.y + bb[3]};
            if (m == 0) {
#pragma unroll
                for (int j = 0; j < 4; j++)
                    g_kT[(size_t)(b * HS + hg * 4 + j) * T + t] = vals[j];
            } else if (m == 1) {
#pragma unroll
                for (int j = 0; j < 4; j++)
                    g_qT[(size_t)(b * HS + hg * 4 + j) * T + t] = vals[j];
            } else {
                *(float4*)(g_v + (size_t)row * HS + hg * 4) =
                    make_float4(vals[0], vals[1], vals[2], vals[3]);
            }
        }
    }
}

// =====================================================================
// K2a: S = 8 * q k^T.  BM=BN=128, 256 threads, microtile 8t x 8v.
// =====================================================================
__global__ __launch_bounds__(256) void qk_kernel()
{
    extern __shared__ float4 sm4[];
    float4* Q4 = sm4;             // [64][32]
    float4* K4 = sm4 + 64 * 32;   // [64][32]

    const int v0  = blockIdx.x * 128;
    const int t0  = blockIdx.y * 128;
    const int b   = blockIdx.z;
    const int tid = threadIdx.x;

    const float4* qT4 = (const float4*)g_qT;
    const float4* kT4 = (const float4*)g_kT;

#pragma unroll
    for (int it = 0; it < 8; it++) {
        int idx = tid + it * 256;
        int c = idx >> 5, x4 = idx & 31;
        Q4[idx] = qT4[(size_t)(b * HS + c) * (T / 4) + (t0 >> 2) + x4];
        K4[idx] = kT4[(size_t)(b * HS + c) * (T / 4) + (v0 >> 2) + x4];
    }
    __syncthreads();

    const int tg = tid >> 4;
    const int vg = tid & 15;

    ull acc[8][4];
#pragma unroll
    for (int i = 0; i < 8; i++)
#pragma unroll
        for (int p = 0; p < 4; p++) acc[i][p] = 0ull;

#pragma unroll 8
    for (int c = 0; c < 64; c++) {
        float4 a0 = Q4[c * 32 + tg * 2];
        float4 a1 = Q4[c * 32 + tg * 2 + 1];
        float4 k0 = K4[c * 32 + vg * 2];
        float4 k1 = K4[c * 32 + vg * 2 + 1];
        ull kp[4] = {pack2(k0.x, k0.y), pack2(k0.z, k0.w),
                     pack2(k1.x, k1.y), pack2(k1.z, k1.w)};
        ull as[8] = {splat2(a0.x), splat2(a0.y), splat2(a0.z), splat2(a0.w),
                     splat2(a1.x), splat2(a1.y), splat2(a1.z), splat2(a1.w)};
#pragma unroll
        for (int i = 0; i < 8; i++)
#pragma unroll
            for (int p = 0; p < 4; p++) ffma2(acc[i][p], as[i], kp[p]);
    }

#pragma unroll
    for (int i = 0; i < 8; i++) {
        int trow = t0 + tg * 8 + i;
        float* srow = g_s + ((size_t)(b * T + trow)) * T + v0 + vg * 8;
        float2 p0 = unpack2(acc[i][0]), p1 = unpack2(acc[i][1]);
        float2 p2 = unpack2(acc[i][2]), p3 = unpack2(acc[i][3]);
        *(float4*)(srow)     = make_float4(8.f * p0.x, 8.f * p0.y, 8.f * p1.x, 8.f * p1.y);
        *(float4*)(srow + 4) = make_float4(8.f * p2.x, 8.f * p2.y, 8.f * p3.x, 8.f * p3.y);
    }
}

// =====================================================================
// K2b: S += q . rel.  grid t. 256 threads = 128 v x 2 b-groups (4b each).
// q pairs in SMEM read via broadcast LDS.128 (NO register array, NO spill).
// rel staged once (1.07 GB total), XOR-swizzled.
// =====================================================================
__global__ __launch_bounds__(256) void rel_kernel(const float* __restrict__ rel)
{
    __shared__ float4 R4[128][16];                    // 32 KB
    __shared__ __align__(16) ull qs2[64][4];          // [c][b-pair] 2 KB

    const int t   = blockIdx.x;
    const int tid = threadIdx.x;

    // stage q pairs: thread (pr = tid>>6, c = tid&63)
    if (tid < 256) {
        int pr = tid >> 6;      // 0..3 -> batches (2pr, 2pr+1)
        int c  = tid & 63;
        float qa = g_qT[(size_t)((2 * pr + 0) * HS + c) * T + t];
        float qb = g_qT[(size_t)((2 * pr + 1) * HS + c) * T + t];
        qs2[c][pr] = pack2(qa, qb);
    }
    __syncthreads();

    const int v  = tid & 127;
    const int bg = tid >> 7;          // 0/1 -> batches bg*4 .. bg*4+3
    const int sw = v & 15;

    const float4* relt = (const float4*)(rel + (size_t)t * T * HS);
    const size_t TT = (size_t)T * T;
    const size_t srow = ((size_t)(bg * 4) * T + t) * T;

    for (int v0 = 0; v0 < T; v0 += 128) {
        __syncthreads();
#pragma unroll
        for (int it = 0; it < 8; it++) {
            int idx = tid + it * 256;     // 0..2047
            int vv  = idx >> 4;
            int c4  = idx & 15;
            R4[vv][c4 ^ (vv & 15)] = relt[(size_t)(v0 + vv) * 16 + c4];
        }
        __syncthreads();

        ull a0 = 0ull, a1 = 0ull;
#pragma unroll
        for (int c4 = 0; c4 < 16; c4++) {
            float4 r4 = R4[v][c4 ^ sw];
            {
                ulonglong2 qq = *(const ulonglong2*)&qs2[c4 * 4 + 0][bg * 2];
                ull rp = splat2(r4.x); ffma2(a0, qq.x, rp); ffma2(a1, qq.y, rp);
            }
            {
                ulonglong2 qq = *(const ulonglong2*)&qs2[c4 * 4 + 1][bg * 2];
                ull rp = splat2(r4.y); ffma2(a0, qq.x, rp); ffma2(a1, qq.y, rp);
            }
            {
                ulonglong2 qq = *(const ulonglong2*)&qs2[c4 * 4 + 2][bg * 2];
                ull rp = splat2(r4.z); ffma2(a0, qq.x, rp); ffma2(a1, qq.y, rp);
            }
            {
                ulonglong2 qq = *(const ulonglong2*)&qs2[c4 * 4 + 3][bg * 2];
                ull rp = splat2(r4.w); ffma2(a0, qq.x, rp); ffma2(a1, qq.y, rp);
            }
        }

        size_t si = srow + v0 + v;
        float2 f0 = unpack2(a0), f1 = unpack2(a1);
        g_s[si]          += f0.x;
        g_s[si + TT]     += f0.y;
        g_s[si + 2 * TT] += f1.x;
        g_s[si + 3 * TT] += f1.y;
    }
}

// =====================================================================
// K3: softmax + PV. 16 t rows / block, 512 threads / 16 warps, 2 CTAs/SM.
// att stored fp16 transposed (stride 17). Partials reuse the att buffer.
// =====================================================================
__global__ __launch_bounds__(512, 2) void soft_pv_kernel(float* __restrict__ out)
{
    extern __shared__ __align__(16) unsigned char smraw[];
    __half* attH = (__half*)smraw;          // [2048][17] fp16 = 69.6 KB
    float*  pout = (float*)smraw;           // reused after sync: [16][16][64] = 64 KB
    __shared__ float invl[16];

    const int t0   = blockIdx.x * 16;
    const int b    = blockIdx.y;
    const int tid  = threadIdx.x;
    const int w    = tid >> 5;      // 0..15
    const int lane = tid & 31;

    // softmax of row w (one warp per row)
    {
        const float4* srow4 = (const float4*)(g_s + ((size_t)(b * T + t0 + w)) * T);
        float m = -3.4e38f;
#pragma unroll
        for (int i = 0; i < 16; i++) {
            float4 sv = srow4[i * 32 + lane];
            m = fmaxf(m, fmaxf(fmaxf(sv.x, sv.y), fmaxf(sv.z, sv.w)));
        }
#pragma unroll
        for (int o = 16; o > 0; o >>= 1)
            m = fmaxf(m, __shfl_xor_sync(0xffffffffu, m, o));

        const float* srow = g_s + ((size_t)(b * T + t0 + w)) * T;
        float sum = 0.f;
#pragma unroll 8
        for (int i = 0; i < 64; i++) {
            int vi = i * 32 + lane;
            float e = __expf(srow[vi] - m);
            attH[vi * 17 + w] = __float2half_rn(e);
            sum += e;
        }
#pragma unroll
        for (int o = 16; o > 0; o >>= 1)
            sum += __shfl_xor_sync(0xffffffffu, sum, o);
        if (lane == 0) invl[w] = 1.f / sum;
    }
    __syncthreads();

    // PV: warp w handles v in [w*128, w*128+128)
    const int th = lane >> 4;    // t-half: rows th*8..th*8+7
    const int hg = lane & 15;    // h = hg*4..hg*4+3
    const float4* vb = (const float4*)(g_v + (size_t)b * T * HS) + hg;

    ull acc[8][2];
#pragma unroll
    for (int j = 0; j < 8; j++) { acc[j][0] = 0ull; acc[j][1] = 0ull; }

    const int vbeg = w * 128;
#pragma unroll 2
    for (int v = vbeg; v < vbeg + 128; v++) {
        float4 vv = vb[(size_t)v * 16];
        ull vp0 = pack2(vv.x, vv.y), vp1 = pack2(vv.z, vv.w);
        const __half* arow = attH + v * 17 + th * 8;
#pragma unroll
        for (int j = 0; j < 8; j++) {
            ull a = splat2(__half2float(arow[j]));
            ffma2(acc[j][0], a, vp0);
            ffma2(acc[j][1], a, vp1);
        }
    }

    __syncthreads();   // all attH reads done before overwriting with partials

    float* pw = pout + w * 1024;
#pragma unroll
    for (int j = 0; j < 8; j++) {
        int tt = th * 8 + j;
        float2 x0 = unpack2(acc[j][0]), x1 = unpack2(acc[j][1]);
        *(float4*)(pw + tt * 64 + hg * 4) = make_float4(x0.x, x0.y, x1.x, x1.y);
    }
    __syncthreads();

    // reduce 16 warps' partials: 512 threads x float2 = 1024 outputs
    {
        int tt = tid >> 5;            // 0..15
        int h2 = (tid & 31) * 2;      // 0..62 step 2
        float2 s = make_float2(0.f, 0.f);
#pragma unroll
        for (int ww = 0; ww < 16; ww++) {
            float2 p = *(float2*)(pout + ww * 1024 + tt * 64 + h2);
            s.x += p.x; s.y += p.y;
        }
        float sc = invl[tt];
        *(float2*)(out + ((size_t)(b * T + t0 + tt)) * HS + h2) =
            make_float2(s.x * sc, s.y * sc);
    }
}

// =====================================================================
extern "C" void kernel_launch(void* const* d_in, const int* in_sizes, int n_in,
                              void* d_out, int out_size)
{
    (void)in_sizes; (void)n_in; (void)out_size;
    const float* x   = (const float*)d_in[0];
    const float* Wk  = (const float*)d_in[1];
    const float* bk  = (const float*)d_in[2];
    const float* Wq  = (const float*)d_in[3];
    const float* bq  = (const float*)d_in[4];
    const float* Wv  = (const float*)d_in[5];
    const float* bv  = (const float*)d_in[6];
    const float* rel = (const float*)d_in[7];
    float* out = (float*)d_out;

    proj_kernel<<<(B * T) / 128, 256>>>(x, Wk, bk, Wq, bq, Wv, bv);

    const int qk_smem = 64 * 32 * 2 * sizeof(float4);   // 64 KB
    cudaFuncSetAttribute(qk_kernel, cudaFuncAttributeMaxDynamicSharedMemorySize, qk_smem);
    qk_kernel<<<dim3(T / 128, T / 128, B), 256, qk_smem>>>();

    rel_kernel<<<T, 256>>>(rel);

    const int k3_smem = 2048 * 17 * (int)sizeof(__half);  // 69.6 KB (>= 64 KB pout)
    cudaFuncSetAttribute(soft_pv_kernel, cudaFuncAttributeMaxDynamicSharedMemorySize, k3_smem);
    soft_pv_kernel<<<dim3(T / 16, B), 512, k3_smem>>>(out);
}

// round 5
// speedup vs baseline: 3.2552x; 1.1195x over previous
#include <cuda_runtime.h>
#include <cuda_fp16.h>

#define B 8
#define T 2048
#define D 1024
#define HS 64

typedef unsigned long long ull;

// ---- device scratch ----
__device__ float g_qT[B * HS * T];           // [b][c][t]
__device__ float g_kT[B * HS * T];           // [b][c][t]
__device__ float g_v [B * T * HS];           // [b][t][h]
__device__ float g_s [(size_t)B * T * T];    // [b][t][v] scores

// ---- packed f32x2 helpers (sm_103a FFMA2) ----
__device__ __forceinline__ ull splat2(float a) {
    ull r; asm("mov.b64 %0, {%1, %1};" : "=l"(r) : "f"(a)); return r;
}
__device__ __forceinline__ ull pack2(float x, float y) {
    ull r; asm("mov.b64 %0, {%1, %2};" : "=l"(r) : "f"(x), "f"(y)); return r;
}
__device__ __forceinline__ void ffma2(ull& d, ull a, ull b) {
    asm("fma.rn.f32x2 %0, %1, %2, %0;" : "+l"(d) : "l"(a), "l"(b));
}
__device__ __forceinline__ float2 unpack2(ull v) {
    float2 f; asm("mov.b64 {%0, %1}, %2;" : "=f"(f.x), "=f"(f.y) : "l"(v)); return f;
}

// =====================================================================
// K1: projections. BM=64 rows (grid 256), 256 threads, microtile 4t x 4h
// x 3 mats. Register double-buffered BK=16 chunks, double smem buffers.
// =====================================================================
__global__ __launch_bounds__(256) void proj_kernel(
    const float* __restrict__ x,
    const float* __restrict__ Wk, const float* __restrict__ bk,
    const float* __restrict__ Wq, const float* __restrict__ bq,
    const float* __restrict__ Wv, const float* __restrict__ bv)
{
    __shared__ float Xs[2][16][68];       // [buf][c][t]
    __shared__ float Ws[2][3][16][68];    // [buf][m][c][h]

    const int m0  = blockIdx.x * 64;
    const int tid = threadIdx.x;
    const int tg  = tid >> 4;   // 0..15 -> t = tg*4
    const int hg  = tid & 15;   // 0..15 -> h = hg*4

    const float* W[3] = {Wk, Wq, Wv};

    const int lr = tid >> 2;          // 0..63
    const int lc = (tid & 3) << 2;    // 0,4,8,12

    ull acc[3][4][2];
#pragma unroll
    for (int m = 0; m < 3; m++)
#pragma unroll
        for (int i = 0; i < 4; i++) { acc[m][i][0] = 0ull; acc[m][i][1] = 0ull; }

    // prologue: load chunk 0, store to buf 0
    float4 rx, rw[3];
    rx = *(const float4*)(x + (size_t)(m0 + lr) * D + lc);
#pragma unroll
    for (int m = 0; m < 3; m++)
        rw[m] = *(const float4*)(W[m] + (size_t)lr * D + lc);

    Xs[0][lc + 0][lr] = rx.x; Xs[0][lc + 1][lr] = rx.y;
    Xs[0][lc + 2][lr] = rx.z; Xs[0][lc + 3][lr] = rx.w;
#pragma unroll
    for (int m = 0; m < 3; m++) {
        Ws[0][m][lc + 0][lr] = rw[m].x; Ws[0][m][lc + 1][lr] = rw[m].y;
        Ws[0][m][lc + 2][lr] = rw[m].z; Ws[0][m][lc + 3][lr] = rw[m].w;
    }
    __syncthreads();

    int buf = 0;
    for (int k0 = 0; k0 < D; k0 += 16) {
        const bool last = (k0 + 16 >= D);
        if (!last) {
            rx = *(const float4*)(x + (size_t)(m0 + lr) * D + k0 + 16 + lc);
#pragma unroll
            for (int m = 0; m < 3; m++)
                rw[m] = *(const float4*)(W[m] + (size_t)lr * D + k0 + 16 + lc);
        }

#pragma unroll
        for (int kk = 0; kk < 16; kk++) {
            float4 a = *(const float4*)&Xs[buf][kk][tg * 4];
            ull as[4] = {splat2(a.x), splat2(a.y), splat2(a.z), splat2(a.w)};
#pragma unroll
            for (int m = 0; m < 3; m++) {
                float4 w = *(const float4*)&Ws[buf][m][kk][hg * 4];
                ull w0 = pack2(w.x, w.y), w1 = pack2(w.z, w.w);
#pragma unroll
                for (int i = 0; i < 4; i++) {
                    ffma2(acc[m][i][0], as[i], w0);
                    ffma2(acc[m][i][1], as[i], w1);
                }
            }
        }

        if (!last) {
            int nb = buf ^ 1;
            Xs[nb][lc + 0][lr] = rx.x; Xs[nb][lc + 1][lr] = rx.y;
            Xs[nb][lc + 2][lr] = rx.z; Xs[nb][lc + 3][lr] = rx.w;
#pragma unroll
            for (int m = 0; m < 3; m++) {
                Ws[nb][m][lc + 0][lr] = rw[m].x; Ws[nb][m][lc + 1][lr] = rw[m].y;
                Ws[nb][m][lc + 2][lr] = rw[m].z; Ws[nb][m][lc + 3][lr] = rw[m].w;
            }
            __syncthreads();
            buf = nb;
        }
    }

    const float* bias[3] = {bk, bq, bv};
    const int b = m0 >> 11;
#pragma unroll
    for (int m = 0; m < 3; m++) {
        float4 bm = *(const float4*)(bias[m] + hg * 4);
        float bb[4] = {bm.x, bm.y, bm.z, bm.w};
#pragma unroll
        for (int i = 0; i < 4; i++) {
            int row = m0 + tg * 4 + i;
            int t   = row & (T - 1);
            float2 v0 = unpack2(acc[m][i][0]);
            float2 v1 = unpack2(acc[m][i][1]);
            float vals[4] = {v0.x + bb[0], v0.y + bb[1], v1.x + bb[2], v1.y + bb[3]};
            if (m == 0) {
#pragma unroll
                for (int j = 0; j < 4; j++)
                    g_kT[(size_t)(b * HS + hg * 4 + j) * T + t] = vals[j];
            } else if (m == 1) {
#pragma unroll
                for (int j = 0; j < 4; j++)
                    g_qT[(size_t)(b * HS + hg * 4 + j) * T + t] = vals[j];
            } else {
                *(float4*)(g_v + (size_t)row * HS + hg * 4) =
                    make_float4(vals[0], vals[1], vals[2], vals[3]);
            }
        }
    }
}

// =====================================================================
// K2a: S = 8 * q k^T.  BM=BN=128, 256 threads, microtile 8t x 8v.
// =====================================================================
__global__ __launch_bounds__(256) void qk_kernel()
{
    extern __shared__ float4 sm4[];
    float4* Q4 = sm4;             // [64][32]
    float4* K4 = sm4 + 64 * 32;   // [64][32]

    const int v0  = blockIdx.x * 128;
    const int t0  = blockIdx.y * 128;
    const int b   = blockIdx.z;
    const int tid = threadIdx.x;

    const float4* qT4 = (const float4*)g_qT;
    const float4* kT4 = (const float4*)g_kT;

#pragma unroll
    for (int it = 0; it < 8; it++) {
        int idx = tid + it * 256;
        int c = idx >> 5, x4 = idx & 31;
        Q4[idx] = qT4[(size_t)(b * HS + c) * (T / 4) + (t0 >> 2) + x4];
        K4[idx] = kT4[(size_t)(b * HS + c) * (T / 4) + (v0 >> 2) + x4];
    }
    __syncthreads();

    const int tg = tid >> 4;
    const int vg = tid & 15;

    ull acc[8][4];
#pragma unroll
    for (int i = 0; i < 8; i++)
#pragma unroll
        for (int p = 0; p < 4; p++) acc[i][p] = 0ull;

#pragma unroll 8
    for (int c = 0; c < 64; c++) {
        float4 a0 = Q4[c * 32 + tg * 2];
        float4 a1 = Q4[c * 32 + tg * 2 + 1];
        float4 k0 = K4[c * 32 + vg * 2];
        float4 k1 = K4[c * 32 + vg * 2 + 1];
        ull kp[4] = {pack2(k0.x, k0.y), pack2(k0.z, k0.w),
                     pack2(k1.x, k1.y), pack2(k1.z, k1.w)};
        ull as[8] = {splat2(a0.x), splat2(a0.y), splat2(a0.z), splat2(a0.w),
                     splat2(a1.x), splat2(a1.y), splat2(a1.z), splat2(a1.w)};
#pragma unroll
        for (int i = 0; i < 8; i++)
#pragma unroll
            for (int p = 0; p < 4; p++) ffma2(acc[i][p], as[i], kp[p]);
    }

#pragma unroll
    for (int i = 0; i < 8; i++) {
        int trow = t0 + tg * 8 + i;
        float* srow = g_s + ((size_t)(b * T + trow)) * T + v0 + vg * 8;
        float2 p0 = unpack2(acc[i][0]), p1 = unpack2(acc[i][1]);
        float2 p2 = unpack2(acc[i][2]), p3 = unpack2(acc[i][3]);
        *(float4*)(srow)     = make_float4(8.f * p0.x, 8.f * p0.y, 8.f * p1.x, 8.f * p1.y);
        *(float4*)(srow + 4) = make_float4(8.f * p2.x, 8.f * p2.y, 8.f * p3.x, 8.f * p3.y);
    }
}

// =====================================================================
// K2b: S += q . rel.  grid t. 256 threads = 128 v x 2 b-groups (4b each).
// q pairs in SMEM (broadcast LDS). rel tiles register double-buffered.
// =====================================================================
__global__ __launch_bounds__(256) void rel_kernel(const float* __restrict__ rel)
{
    __shared__ float4 R4[128][16];                    // 32 KB
    __shared__ __align__(16) ull qs2[64][4];          // 2 KB

    const int t   = blockIdx.x;
    const int tid = threadIdx.x;

    // stage q pairs
    {
        int pr = tid >> 6;      // 0..3 -> batches (2pr, 2pr+1)
        int c  = tid & 63;
        float qa = g_qT[(size_t)((2 * pr + 0) * HS + c) * T + t];
        float qb = g_qT[(size_t)((2 * pr + 1) * HS + c) * T + t];
        qs2[c][pr] = pack2(qa, qb);
    }

    const int v  = tid & 127;
    const int bg = tid >> 7;
    const int sw = v & 15;

    const float4* relt = (const float4*)(rel + (size_t)t * T * HS);
    const size_t TT = (size_t)T * T;
    const size_t srow = ((size_t)(bg * 4) * T + t) * T;

    const int lvv = tid >> 4;        // 0..15 base row (+128/it handled below)
    const int lc4 = tid & 15;

    // prologue: tile 0 -> smem
    float4 r[8];
#pragma unroll
    for (int it = 0; it < 8; it++)
        r[it] = relt[(size_t)(lvv + it * 16) * 16 + lc4];
#pragma unroll
    for (int it = 0; it < 8; it++) {
        int vv = lvv + it * 16;
        R4[vv][lc4 ^ (vv & 15)] = r[it];
    }
    __syncthreads();

    for (int v0 = 0; v0 < T; v0 += 128) {
        const bool last = (v0 + 128 >= T);
        if (!last) {
#pragma unroll
            for (int it = 0; it < 8; it++)
                r[it] = relt[(size_t)(v0 + 128 + lvv + it * 16) * 16 + lc4];
        }

        // prefetch S for RMW
        size_t si = srow + v0 + v;
        float s0 = g_s[si], s1 = g_s[si + TT], s2 = g_s[si + 2 * TT], s3 = g_s[si + 3 * TT];

        ull a0 = 0ull, a1 = 0ull;
#pragma unroll
        for (int c4 = 0; c4 < 16; c4++) {
            float4 r4 = R4[v][c4 ^ sw];
            {
                ulonglong2 qq = *(const ulonglong2*)&qs2[c4 * 4 + 0][bg * 2];
                ull rp = splat2(r4.x); ffma2(a0, qq.x, rp); ffma2(a1, qq.y, rp);
            }
            {
                ulonglong2 qq = *(const ulonglong2*)&qs2[c4 * 4 + 1][bg * 2];
                ull rp = splat2(r4.y); ffma2(a0, qq.x, rp); ffma2(a1, qq.y, rp);
            }
            {
                ulonglong2 qq = *(const ulonglong2*)&qs2[c4 * 4 + 2][bg * 2];
                ull rp = splat2(r4.z); ffma2(a0, qq.x, rp); ffma2(a1, qq.y, rp);
            }
            {
                ulonglong2 qq = *(const ulonglong2*)&qs2[c4 * 4 + 3][bg * 2];
                ull rp = splat2(r4.w); ffma2(a0, qq.x, rp); ffma2(a1, qq.y, rp);
            }
        }

        float2 f0 = unpack2(a0), f1 = unpack2(a1);
        g_s[si]          = s0 + f0.x;
        g_s[si + TT]     = s1 + f0.y;
        g_s[si + 2 * TT] = s2 + f1.x;
        g_s[si + 3 * TT] = s3 + f1.y;

        __syncthreads();   // all reads of current tile done
        if (!last) {
#pragma unroll
            for (int it = 0; it < 8; it++) {
                int vv = lvv + it * 16;
                R4[vv][lc4 ^ (vv & 15)] = r[it];
            }
            __syncthreads();
        }
    }
}

// =====================================================================
// K3: softmax + PV. 16 t rows / block, 512 threads / 16 warps, 2 CTAs/SM.
// att fp16, row stride 24 halves (16B aligned) -> PV reads LDS.128.
// =====================================================================
__global__ __launch_bounds__(512, 2) void soft_pv_kernel(float* __restrict__ out)
{
    extern __shared__ __align__(16) unsigned char smraw[];
    __half* attH = (__half*)smraw;          // [2048][24] fp16 = 96 KB
    float*  pout = (float*)smraw;           // reused after sync: [16][16][64] = 64 KB
    __shared__ float invl[16];

    const int t0   = blockIdx.x * 16;
    const int b    = blockIdx.y;
    const int tid  = threadIdx.x;
    const int w    = tid >> 5;      // 0..15
    const int lane = tid & 31;

    // softmax of row w (one warp per row)
    {
        const float4* srow4 = (const float4*)(g_s + ((size_t)(b * T + t0 + w)) * T);
        float m = -3.4e38f;
#pragma unroll
        for (int i = 0; i < 16; i++) {
            float4 sv = srow4[i * 32 + lane];
            m = fmaxf(m, fmaxf(fmaxf(sv.x, sv.y), fmaxf(sv.z, sv.w)));
        }
#pragma unroll
        for (int o = 16; o > 0; o >>= 1)
            m = fmaxf(m, __shfl_xor_sync(0xffffffffu, m, o));

        const float* srow = g_s + ((size_t)(b * T + t0 + w)) * T;
        float sum = 0.f;
#pragma unroll 8
        for (int i = 0; i < 64; i++) {
            int vi = i * 32 + lane;
            float e = __expf(srow[vi] - m);
            attH[vi * 24 + w] = __float2half_rn(e);
            sum += e;
        }
#pragma unroll
        for (int o = 16; o > 0; o >>= 1)
            sum += __shfl_xor_sync(0xffffffffu, sum, o);
        if (lane == 0) invl[w] = 1.f / sum;
    }
    __syncthreads();

    // PV: warp w handles v in [w*128, w*128+128)
    const int th = lane >> 4;    // t-half: rows th*8..th*8+7
    const int hg = lane & 15;    // h = hg*4..hg*4+3
    const float4* vb = (const float4*)(g_v + (size_t)b * T * HS) + hg;

    ull acc[8][2];
#pragma unroll
    for (int j = 0; j < 8; j++) { acc[j][0] = 0ull; acc[j][1] = 0ull; }

    const int vbeg = w * 128;
#pragma unroll 2
    for (int v = vbeg; v < vbeg + 128; v++) {
        float4 vv = vb[(size_t)v * 16];
        ull vp0 = pack2(vv.x, vv.y), vp1 = pack2(vv.z, vv.w);
        uint4 raw = *(const uint4*)(attH + v * 24 + th * 8);   // 8 halves
        const __half2* h2 = (const __half2*)&raw;
#pragma unroll
        for (int jj = 0; jj < 4; jj++) {
            float2 f = __half22float2(h2[jj]);
            ull aa = splat2(f.x);
            ffma2(acc[2 * jj][0], aa, vp0);
            ffma2(acc[2 * jj][1], aa, vp1);
            ull ab = splat2(f.y);
            ffma2(acc[2 * jj + 1][0], ab, vp0);
            ffma2(acc[2 * jj + 1][1], ab, vp1);
        }
    }

    __syncthreads();   // all attH reads done before overwriting with partials

    float* pw = pout + w * 1024;
#pragma unroll
    for (int j = 0; j < 8; j++) {
        int tt = th * 8 + j;
        float2 x0 = unpack2(acc[j][0]), x1 = unpack2(acc[j][1]);
        *(float4*)(pw + tt * 64 + hg * 4) = make_float4(x0.x, x0.y, x1.x, x1.y);
    }
    __syncthreads();

    // reduce 16 warps' partials
    {
        int tt = tid >> 5;            // 0..15
        int h2i = (tid & 31) * 2;     // 0..62 step 2
        float2 s = make_float2(0.f, 0.f);
#pragma unroll
        for (int ww = 0; ww < 16; ww++) {
            float2 p = *(float2*)(pout + ww * 1024 + tt * 64 + h2i);
            s.x += p.x; s.y += p.y;
        }
        float sc = invl[tt];
        *(float2*)(out + ((size_t)(b * T + t0 + tt)) * HS + h2i) =
            make_float2(s.x * sc, s.y * sc);
    }
}

// =====================================================================
extern "C" void kernel_launch(void* const* d_in, const int* in_sizes, int n_in,
                              void* d_out, int out_size)
{
    (void)in_sizes; (void)n_in; (void)out_size;
    const float* x   = (const float*)d_in[0];
    const float* Wk  = (const float*)d_in[1];
    const float* bk  = (const float*)d_in[2];
    const float* Wq  = (const float*)d_in[3];
    const float* bq  = (const float*)d_in[4];
    const float* Wv  = (const float*)d_in[5];
    const float* bv  = (const float*)d_in[6];
    const float* rel = (const float*)d_in[7];
    float* out = (float*)d_out;

    proj_kernel<<<(B * T) / 64, 256>>>(x, Wk, bk, Wq, bq, Wv, bv);

    const int qk_smem = 64 * 32 * 2 * sizeof(float4);   // 64 KB
    cudaFuncSetAttribute(qk_kernel, cudaFuncAttributeMaxDynamicSharedMemorySize, qk_smem);
    qk_kernel<<<dim3(T / 128, T / 128, B), 256, qk_smem>>>();

    rel_kernel<<<T, 256>>>(rel);

    const int k3_smem = 2048 * 24 * (int)sizeof(__half);  // 96 KB
    cudaFuncSetAttribute(soft_pv_kernel, cudaFuncAttributeMaxDynamicSharedMemorySize, k3_smem);
    soft_pv_kernel<<<dim3(T / 16, B), 512, k3_smem>>>(out);
}

// round 6
// speedup vs baseline: 3.3516x; 1.0296x over previous
#include <cuda_runtime.h>
#include <cuda_fp16.h>

#define B 8
#define T 2048
#define D 1024
#define HS 64

typedef unsigned long long ull;

// ---- device scratch ----
__device__ float g_qT[B * HS * T];           // [b][c][t]
__device__ float g_kT[B * HS * T];           // [b][c][t]
__device__ float g_v [B * T * HS];           // [b][t][h]
__device__ float g_s [(size_t)B * T * T];    // [b][t][v] scores

// ---- packed f32x2 helpers (sm_103a FFMA2) ----
__device__ __forceinline__ ull splat2(float a) {
    ull r; asm("mov.b64 %0, {%1, %1};" : "=l"(r) : "f"(a)); return r;
}
__device__ __forceinline__ ull pack2(float x, float y) {
    ull r; asm("mov.b64 %0, {%1, %2};" : "=l"(r) : "f"(x), "f"(y)); return r;
}
__device__ __forceinline__ void ffma2(ull& d, ull a, ull b) {
    asm("fma.rn.f32x2 %0, %1, %2, %0;" : "+l"(d) : "l"(a), "l"(b));
}
__device__ __forceinline__ float2 unpack2(ull v) {
    float2 f; asm("mov.b64 {%0, %1}, %2;" : "=f"(f.x), "=f"(f.y) : "l"(v)); return f;
}
__device__ __forceinline__ void cp_async16(void* smem_dst, const void* gmem_src) {
    unsigned sa = (unsigned)__cvta_generic_to_shared(smem_dst);
    asm volatile("cp.async.cg.shared.global [%0], [%1], 16;" :: "r"(sa), "l"(gmem_src) : "memory");
}
__device__ __forceinline__ void cp_commit() {
    asm volatile("cp.async.commit_group;" ::: "memory");
}
template<int N> __device__ __forceinline__ void cp_wait() {
    asm volatile("cp.async.wait_group %0;" :: "n"(N) : "memory");
}

// =====================================================================
// K1: projections. BM=64 rows, 256 threads, microtile 4t x 4h x 3 mats.
// Register double-buffered BK=16 chunks. (unchanged from R5)
// =====================================================================
__global__ __launch_bounds__(256) void proj_kernel(
    const float* __restrict__ x,
    const float* __restrict__ Wk, const float* __restrict__ bk,
    const float* __restrict__ Wq, const float* __restrict__ bq,
    const float* __restrict__ Wv, const float* __restrict__ bv)
{
    __shared__ float Xs[2][16][68];
    __shared__ float Ws[2][3][16][68];

    const int m0  = blockIdx.x * 64;
    const int tid = threadIdx.x;
    const int tg  = tid >> 4;
    const int hg  = tid & 15;

    const float* W[3] = {Wk, Wq, Wv};

    const int lr = tid >> 2;
    const int lc = (tid & 3) << 2;

    ull acc[3][4][2];
#pragma unroll
    for (int m = 0; m < 3; m++)
#pragma unroll
        for (int i = 0; i < 4; i++) { acc[m][i][0] = 0ull; acc[m][i][1] = 0ull; }

    float4 rx, rw[3];
    rx = *(const float4*)(x + (size_t)(m0 + lr) * D + lc);
#pragma unroll
    for (int m = 0; m < 3; m++)
        rw[m] = *(const float4*)(W[m] + (size_t)lr * D + lc);

    Xs[0][lc + 0][lr] = rx.x; Xs[0][lc + 1][lr] = rx.y;
    Xs[0][lc + 2][lr] = rx.z; Xs[0][lc + 3][lr] = rx.w;
#pragma unroll
    for (int m = 0; m < 3; m++) {
        Ws[0][m][lc + 0][lr] = rw[m].x; Ws[0][m][lc + 1][lr] = rw[m].y;
        Ws[0][m][lc + 2][lr] = rw[m].z; Ws[0][m][lc + 3][lr] = rw[m].w;
    }
    __syncthreads();

    int buf = 0;
    for (int k0 = 0; k0 < D; k0 += 16) {
        const bool last = (k0 + 16 >= D);
        if (!last) {
            rx = *(const float4*)(x + (size_t)(m0 + lr) * D + k0 + 16 + lc);
#pragma unroll
            for (int m = 0; m < 3; m++)
                rw[m] = *(const float4*)(W[m] + (size_t)lr * D + k0 + 16 + lc);
        }

#pragma unroll
        for (int kk = 0; kk < 16; kk++) {
            float4 a = *(const float4*)&Xs[buf][kk][tg * 4];
            ull as[4] = {splat2(a.x), splat2(a.y), splat2(a.z), splat2(a.w)};
#pragma unroll
            for (int m = 0; m < 3; m++) {
                float4 w = *(const float4*)&Ws[buf][m][kk][hg * 4];
                ull w0 = pack2(w.x, w.y), w1 = pack2(w.z, w.w);
#pragma unroll
                for (int i = 0; i < 4; i++) {
                    ffma2(acc[m][i][0], as[i], w0);
                    ffma2(acc[m][i][1], as[i], w1);
                }
            }
        }

        if (!last) {
            int nb = buf ^ 1;
            Xs[nb][lc + 0][lr] = rx.x; Xs[nb][lc + 1][lr] = rx.y;
            Xs[nb][lc + 2][lr] = rx.z; Xs[nb][lc + 3][lr] = rx.w;
#pragma unroll
            for (int m = 0; m < 3; m++) {
                Ws[nb][m][lc + 0][lr] = rw[m].x; Ws[nb][m][lc + 1][lr] = rw[m].y;
                Ws[nb][m][lc + 2][lr] = rw[m].z; Ws[nb][m][lc + 3][lr] = rw[m].w;
            }
            __syncthreads();
            buf = nb;
        }
    }

    const float* bias[3] = {bk, bq, bv};
    const int b = m0 >> 11;
#pragma unroll
    for (int m = 0; m < 3; m++) {
        float4 bm = *(const float4*)(bias[m] + hg * 4);
        float bb[4] = {bm.x, bm.y, bm.z, bm.w};
#pragma unroll
        for (int i = 0; i < 4; i++) {
            int row = m0 + tg * 4 + i;
            int t   = row & (T - 1);
            float2 v0 = unpack2(acc[m][i][0]);
            float2 v1 = unpack2(acc[m][i][1]);
            float vals[4] = {v0.x + bb[0], v0.y + bb[1], v1.x + bb[2], v1.y + bb[3]};
            if (m == 0) {
#pragma unroll
                for (int j = 0; j < 4; j++)
                    g_kT[(size_t)(b * HS + hg * 4 + j) * T + t] = vals[j];
            } else if (m == 1) {
#pragma unroll
                for (int j = 0; j < 4; j++)
                    g_qT[(size_t)(b * HS + hg * 4 + j) * T + t] = vals[j];
            } else {
                *(float4*)(g_v + (size_t)row * HS + hg * 4) =
                    make_float4(vals[0], vals[1], vals[2], vals[3]);
            }
        }
    }
}

// =====================================================================
// K2a: S = 8 * q k^T.  BM=128 t, BN=256 v, 256 threads, microtile 8t x 16v.
// j-major permuted smem layout -> conflict-free 16B-lane-stride LDS.
// =====================================================================
__global__ __launch_bounds__(256, 1) void qk_kernel()
{
    extern __shared__ float4 sm4[];
    float4* Q4 = sm4;             // [64 c][32 t4] perm: idx = (x&1)*16 + (x>>1)
    float4* K4 = sm4 + 64 * 32;   // [64 c][64 v4] perm: idx = (x&3)*16 + (x>>2)

    const int v0  = blockIdx.x * 256;
    const int t0  = blockIdx.y * 128;
    const int b   = blockIdx.z;
    const int tid = threadIdx.x;

    const float4* qT4 = (const float4*)g_qT;
    const float4* kT4 = (const float4*)g_kT;

#pragma unroll
    for (int it = 0; it < 8; it++) {
        int idx = tid + it * 256;            // 0..2047
        int c = idx >> 5, x4 = idx & 31;
        int perm = ((x4 & 1) << 4) | (x4 >> 1);
        Q4[c * 32 + perm] = qT4[(size_t)(b * HS + c) * (T / 4) + (t0 >> 2) + x4];
    }
#pragma unroll
    for (int it = 0; it < 16; it++) {
        int idx = tid + it * 256;            // 0..4095
        int c = idx >> 6, x4 = idx & 63;
        int perm = ((x4 & 3) << 4) | (x4 >> 2);
        K4[c * 64 + perm] = kT4[(size_t)(b * HS + c) * (T / 4) + (v0 >> 2) + x4];
    }
    __syncthreads();

    const int tg = tid >> 4;   // t = tg*8
    const int vg = tid & 15;   // v = vg*16

    ull acc[8][8];
#pragma unroll
    for (int i = 0; i < 8; i++)
#pragma unroll
        for (int p = 0; p < 8; p++) acc[i][p] = 0ull;

#pragma unroll 4
    for (int c = 0; c < 64; c++) {
        float4 qa = Q4[c * 32 + tg];          // t 8tg.. (even t4)
        float4 qb = Q4[c * 32 + 16 + tg];     // odd t4
        float4 k0 = K4[c * 64 + vg];
        float4 k1 = K4[c * 64 + 16 + vg];
        float4 k2 = K4[c * 64 + 32 + vg];
        float4 k3 = K4[c * 64 + 48 + vg];
        ull as[8] = {splat2(qa.x), splat2(qa.y), splat2(qa.z), splat2(qa.w),
                     splat2(qb.x), splat2(qb.y), splat2(qb.z), splat2(qb.w)};
        ull kp[8] = {pack2(k0.x, k0.y), pack2(k0.z, k0.w),
                     pack2(k1.x, k1.y), pack2(k1.z, k1.w),
                     pack2(k2.x, k2.y), pack2(k2.z, k2.w),
                     pack2(k3.x, k3.y), pack2(k3.z, k3.w)};
#pragma unroll
        for (int i = 0; i < 8; i++)
#pragma unroll
            for (int p = 0; p < 8; p++) ffma2(acc[i][p], as[i], kp[p]);
    }

#pragma unroll
    for (int i = 0; i < 8; i++) {
        int trow = t0 + tg * 8 + i;
        float* srow = g_s + ((size_t)(b * T + trow)) * T + v0 + vg * 16;
#pragma unroll
        for (int p = 0; p < 4; p++) {
            float2 e0 = unpack2(acc[i][2 * p]), e1 = unpack2(acc[i][2 * p + 1]);
            *(float4*)(srow + 4 * p) =
                make_float4(8.f * e0.x, 8.f * e0.y, 8.f * e1.x, 8.f * e1.y);
        }
    }
}

// =====================================================================
// K2b: S += q . rel.  grid t. 256 threads, thread = 1 v x 4 b-pairs.
// rel read ONCE via cp.async double-buffered 256-v tiles.
// =====================================================================
__global__ __launch_bounds__(256, 1) void rel_kernel(const float* __restrict__ rel)
{
    __shared__ float4 R4[2][256][16];                 // 128 KB, XOR-swizzled
    __shared__ __align__(16) ull qsP[4][64];          // [pair][c] 2 KB

    const int t   = blockIdx.x;
    const int tid = threadIdx.x;

    // stage q pairs: thread (pr = tid>>6, c = tid&63)
    {
        int pr = tid >> 6;
        int c  = tid & 63;
        float qa = g_qT[(size_t)((2 * pr + 0) * HS + c) * T + t];
        float qb = g_qT[(size_t)((2 * pr + 1) * HS + c) * T + t];
        qsP[pr][c] = pack2(qa, qb);
    }

    const int v  = tid;          // 0..255 within tile
    const int sw = tid & 15;

    const float4* relt = (const float4*)(rel + (size_t)t * T * HS);
    const size_t TT = (size_t)T * T;
    const size_t srow0 = (size_t)t * T;   // + b*TT

    // tile prefetch helper indices: thread stages 16 float4
    const int lvv = tid >> 4;    // base row 0..15 (+16 per it)
    const int lc4 = tid & 15;

    // prefetch tile 0
#pragma unroll
    for (int it = 0; it < 16; it++) {
        int vv = lvv + it * 16;
        cp_async16(&R4[0][vv][lc4 ^ (vv & 15)], &relt[(size_t)vv * 16 + lc4]);
    }
    cp_commit();

    const int NT = T / 256;   // 8 tiles
    for (int n = 0; n < NT; n++) {
        int buf = n & 1;
        if (n + 1 < NT) {
#pragma unroll
            for (int it = 0; it < 16; it++) {
                int vv = lvv + it * 16;
                cp_async16(&R4[buf ^ 1][vv][lc4 ^ (vv & 15)],
                           &relt[(size_t)((n + 1) * 256 + vv) * 16 + lc4]);
            }
            cp_commit();
            cp_wait<1>();
        } else {
            cp_wait<0>();
        }
        __syncthreads();

        // prefetch S values for RMW (8 rows: 4 pairs x 2 batches)
        size_t si = srow0 + n * 256 + v;
        float s[8];
#pragma unroll
        for (int bb = 0; bb < 8; bb++) s[bb] = g_s[si + (size_t)bb * TT];

        ull acc[4] = {0ull, 0ull, 0ull, 0ull};
#pragma unroll
        for (int c4 = 0; c4 < 16; c4++) {
            float4 r4 = R4[buf][v][c4 ^ sw];
            ull rx = splat2(r4.x), ry = splat2(r4.y), rz = splat2(r4.z), rw = splat2(r4.w);
#pragma unroll
            for (int pr = 0; pr < 4; pr++) {
                ulonglong2 qa = *(const ulonglong2*)&qsP[pr][c4 * 4];
                ulonglong2 qb = *(const ulonglong2*)&qsP[pr][c4 * 4 + 2];
                ffma2(acc[pr], qa.x, rx);
                ffma2(acc[pr], qa.y, ry);
                ffma2(acc[pr], qb.x, rz);
                ffma2(acc[pr], qb.y, rw);
            }
        }

#pragma unroll
        for (int pr = 0; pr < 4; pr++) {
            float2 f = unpack2(acc[pr]);
            g_s[si + (size_t)(2 * pr + 0) * TT] = s[2 * pr + 0] + f.x;
            g_s[si + (size_t)(2 * pr + 1) * TT] = s[2 * pr + 1] + f.y;
        }
        __syncthreads();   // protect buf before it is overwritten by prefetch n+2
    }
}

// =====================================================================
// K3: softmax + PV. 16 t rows / block, 512 threads / 16 warps, 2 CTAs/SM.
// att fp16 stride 24; PV acc packed over t (half2 -> float2 direct).
// =====================================================================
__global__ __launch_bounds__(512, 2) void soft_pv_kernel(float* __restrict__ out)
{
    extern __shared__ __align__(16) unsigned char smraw[];
    __half* attH = (__half*)smraw;          // [2048][24] fp16 = 96 KB
    float*  pout = (float*)smraw;           // reused after sync: [16][16][64] = 64 KB
    __shared__ float invl[16];

    const int t0   = blockIdx.x * 16;
    const int b    = blockIdx.y;
    const int tid  = threadIdx.x;
    const int w    = tid >> 5;      // 0..15
    const int lane = tid & 31;

    // softmax of row w (one warp per row)
    {
        const float4* srow4 = (const float4*)(g_s + ((size_t)(b * T + t0 + w)) * T);
        float m = -3.4e38f;
#pragma unroll
        for (int i = 0; i < 16; i++) {
            float4 sv = srow4[i * 32 + lane];
            m = fmaxf(m, fmaxf(fmaxf(sv.x, sv.y), fmaxf(sv.z, sv.w)));
        }
#pragma unroll
        for (int o = 16; o > 0; o >>= 1)
            m = fmaxf(m, __shfl_xor_sync(0xffffffffu, m, o));

        const float* srow = g_s + ((size_t)(b * T + t0 + w)) * T;
        float sum = 0.f;
#pragma unroll 8
        for (int i = 0; i < 64; i++) {
            int vi = i * 32 + lane;
            float e = __expf(srow[vi] - m);
            attH[vi * 24 + w] = __float2half_rn(e);
            sum += e;
        }
#pragma unroll
        for (int o = 16; o > 0; o >>= 1)
            sum += __shfl_xor_sync(0xffffffffu, sum, o);
        if (lane == 0) invl[w] = 1.f / sum;
    }
    __syncthreads();

    // PV: warp w handles v in [w*128, w*128+128)
    const int th = lane >> 4;    // t-half: rows th*8..th*8+7
    const int hg = lane & 15;    // h = hg*4..hg*4+3
    const float4* vb = (const float4*)(g_v + (size_t)b * T * HS) + hg;

    // acc[tp][h]: packed over (t = th*8+2tp, +1), h scalar
    ull acc[4][4];
#pragma unroll
    for (int tp = 0; tp < 4; tp++)
#pragma unroll
        for (int h = 0; h < 4; h++) acc[tp][h] = 0ull;

    const int vbeg = w * 128;
#pragma unroll 2
    for (int v = vbeg; v < vbeg + 128; v++) {
        float4 vv = vb[(size_t)v * 16];
        ull sv[4] = {splat2(vv.x), splat2(vv.y), splat2(vv.z), splat2(vv.w)};
        uint4 raw = *(const uint4*)(attH + v * 24 + th * 8);   // 8 halves = 4 half2
        const __half2* h2 = (const __half2*)&raw;
#pragma unroll
        for (int tp = 0; tp < 4; tp++) {
            float2 f = __half22float2(h2[tp]);
            ull ap = pack2(f.x, f.y);
#pragma unroll
            for (int h = 0; h < 4; h++) ffma2(acc[tp][h], ap, sv[h]);
        }
    }

    __syncthreads();   // all attH reads done before overwriting with partials

    float* pw = pout + w * 1024;
#pragma unroll
    for (int tp = 0; tp < 4; tp++) {
        int r0 = th * 8 + 2 * tp;
        float2 f0 = unpack2(acc[tp][0]), f1 = unpack2(acc[tp][1]);
        float2 f2 = unpack2(acc[tp][2]), f3 = unpack2(acc[tp][3]);
        *(float4*)(pw + r0 * 64 + hg * 4)       = make_float4(f0.x, f1.x, f2.x, f3.x);
        *(float4*)(pw + (r0 + 1) * 64 + hg * 4) = make_float4(f0.y, f1.y, f2.y, f3.y);
    }
    __syncthreads();

    // reduce 16 warps' partials
    {
        int tt = tid >> 5;            // 0..15
        int h2i = (tid & 31) * 2;     // 0..62 step 2
        float2 s = make_float2(0.f, 0.f);
#pragma unroll
        for (int ww = 0; ww < 16; ww++) {
            float2 p = *(float2*)(pout + ww * 1024 + tt * 64 + h2i);
            s.x += p.x; s.y += p.y;
        }
        float sc = invl[tt];
        *(float2*)(out + ((size_t)(b * T + t0 + tt)) * HS + h2i) =
            make_float2(s.x * sc, s.y * sc);
    }
}

// =====================================================================
extern "C" void kernel_launch(void* const* d_in, const int* in_sizes, int n_in,
                              void* d_out, int out_size)
{
    (void)in_sizes; (void)n_in; (void)out_size;
    const float* x   = (const float*)d_in[0];
    const float* Wk  = (const float*)d_in[1];
    const float* bk  = (const float*)d_in[2];
    const float* Wq  = (const float*)d_in[3];
    const float* bq  = (const float*)d_in[4];
    const float* Wv  = (const float*)d_in[5];
    const float* bv  = (const float*)d_in[6];
    const float* rel = (const float*)d_in[7];
    float* out = (float*)d_out;

    proj_kernel<<<(B * T) / 64, 256>>>(x, Wk, bk, Wq, bq, Wv, bv);

    const int qk_smem = (64 * 32 + 64 * 64) * sizeof(float4);   // 96 KB
    cudaFuncSetAttribute(qk_kernel, cudaFuncAttributeMaxDynamicSharedMemorySize, qk_smem);
    qk_kernel<<<dim3(T / 256, T / 128, B), 256, qk_smem>>>();

    rel_kernel<<<T, 256>>>(rel);

    const int k3_smem = 2048 * 24 * (int)sizeof(__half);  // 96 KB
    cudaFuncSetAttribute(soft_pv_kernel, cudaFuncAttributeMaxDynamicSharedMemorySize, k3_smem);
    soft_pv_kernel<<<dim3(T / 16, B), 512, k3_smem>>>(out);
}

// round 7
// speedup vs baseline: 3.3611x; 1.0028x over previous
#include <cuda_runtime.h>
#include <cuda_fp16.h>

#define B 8
#define T 2048
#define D 1024
#define HS 64

typedef unsigned long long ull;

// ---- device scratch ----
__device__ float g_qT[B * HS * T];           // [b][c][t]
__device__ float g_kT[B * HS * T];           // [b][c][t]
__device__ float g_v [B * T * HS];           // [b][t][h]
__device__ float g_s [(size_t)B * T * T];    // [b][t][v] scores

// ---- packed f32x2 helpers (sm_103a FFMA2) ----
__device__ __forceinline__ ull splat2(float a) {
    ull r; asm("mov.b64 %0, {%1, %1};" : "=l"(r) : "f"(a)); return r;
}
__device__ __forceinline__ ull pack2(float x, float y) {
    ull r; asm("mov.b64 %0, {%1, %2};" : "=l"(r) : "f"(x), "f"(y)); return r;
}
__device__ __forceinline__ void ffma2(ull& d, ull a, ull b) {
    asm("fma.rn.f32x2 %0, %1, %2, %0;" : "+l"(d) : "l"(a), "l"(b));
}
__device__ __forceinline__ float2 unpack2(ull v) {
    float2 f; asm("mov.b64 {%0, %1}, %2;" : "=f"(f.x), "=f"(f.y) : "l"(v)); return f;
}
__device__ __forceinline__ void cp_async16(void* smem_dst, const void* gmem_src) {
    unsigned sa = (unsigned)__cvta_generic_to_shared(smem_dst);
    asm volatile("cp.async.cg.shared.global [%0], [%1], 16;" :: "r"(sa), "l"(gmem_src) : "memory");
}
__device__ __forceinline__ void cp_commit() {
    asm volatile("cp.async.commit_group;" ::: "memory");
}
template<int N> __device__ __forceinline__ void cp_wait() {
    asm volatile("cp.async.wait_group %0;" :: "n"(N) : "memory");
}

// =====================================================================
// K1: projections. BM=64 rows, 256 threads, microtile 4t x 4h x 3 mats.
// Register double-buffered BK=16 chunks. (unchanged from R5)
// =====================================================================
__global__ __launch_bounds__(256) void proj_kernel(
    const float* __restrict__ x,
    const float* __restrict__ Wk, const float* __restrict__ bk,
    const float* __restrict__ Wq, const float* __restrict__ bq,
    const float* __restrict__ Wv, const float* __restrict__ bv)
{
    __shared__ float Xs[2][16][68];
    __shared__ float Ws[2][3][16][68];

    const int m0  = blockIdx.x * 64;
    const int tid = threadIdx.x;
    const int tg  = tid >> 4;
    const int hg  = tid & 15;

    const float* W[3] = {Wk, Wq, Wv};

    const int lr = tid >> 2;
    const int lc = (tid & 3) << 2;

    ull acc[3][4][2];
#pragma unroll
    for (int m = 0; m < 3; m++)
#pragma unroll
        for (int i = 0; i < 4; i++) { acc[m][i][0] = 0ull; acc[m][i][1] = 0ull; }

    float4 rx, rw[3];
    rx = *(const float4*)(x + (size_t)(m0 + lr) * D + lc);
#pragma unroll
    for (int m = 0; m < 3; m++)
        rw[m] = *(const float4*)(W[m] + (size_t)lr * D + lc);

    Xs[0][lc + 0][lr] = rx.x; Xs[0][lc + 1][lr] = rx.y;
    Xs[0][lc + 2][lr] = rx.z; Xs[0][lc + 3][lr] = rx.w;
#pragma unroll
    for (int m = 0; m < 3; m++) {
        Ws[0][m][lc + 0][lr] = rw[m].x; Ws[0][m][lc + 1][lr] = rw[m].y;
        Ws[0][m][lc + 2][lr] = rw[m].z; Ws[0][m][lc + 3][lr] = rw[m].w;
    }
    __syncthreads();

    int buf = 0;
    for (int k0 = 0; k0 < D; k0 += 16) {
        const bool last = (k0 + 16 >= D);
        if (!last) {
            rx = *(const float4*)(x + (size_t)(m0 + lr) * D + k0 + 16 + lc);
#pragma unroll
            for (int m = 0; m < 3; m++)
                rw[m] = *(const float4*)(W[m] + (size_t)lr * D + k0 + 16 + lc);
        }

#pragma unroll
        for (int kk = 0; kk < 16; kk++) {
            float4 a = *(const float4*)&Xs[buf][kk][tg * 4];
            ull as[4] = {splat2(a.x), splat2(a.y), splat2(a.z), splat2(a.w)};
#pragma unroll
            for (int m = 0; m < 3; m++) {
                float4 w = *(const float4*)&Ws[buf][m][kk][hg * 4];
                ull w0 = pack2(w.x, w.y), w1 = pack2(w.z, w.w);
#pragma unroll
                for (int i = 0; i < 4; i++) {
                    ffma2(acc[m][i][0], as[i], w0);
                    ffma2(acc[m][i][1], as[i], w1);
                }
            }
        }

        if (!last) {
            int nb = buf ^ 1;
            Xs[nb][lc + 0][lr] = rx.x; Xs[nb][lc + 1][lr] = rx.y;
            Xs[nb][lc + 2][lr] = rx.z; Xs[nb][lc + 3][lr] = rx.w;
#pragma unroll
            for (int m = 0; m < 3; m++) {
                Ws[nb][m][lc + 0][lr] = rw[m].x; Ws[nb][m][lc + 1][lr] = rw[m].y;
                Ws[nb][m][lc + 2][lr] = rw[m].z; Ws[nb][m][lc + 3][lr] = rw[m].w;
            }
            __syncthreads();
            buf = nb;
        }
    }

    const float* bias[3] = {bk, bq, bv};
    const int b = m0 >> 11;
#pragma unroll
    for (int m = 0; m < 3; m++) {
        float4 bm = *(const float4*)(bias[m] + hg * 4);
        float bb[4] = {bm.x, bm.y, bm.z, bm.w};
#pragma unroll
        for (int i = 0; i < 4; i++) {
            int row = m0 + tg * 4 + i;
            int t   = row & (T - 1);
            float2 v0 = unpack2(acc[m][i][0]);
            float2 v1 = unpack2(acc[m][i][1]);
            float vals[4] = {v0.x + bb[0], v0.y + bb[1], v1.x + bb[2], v1.y + bb[3]};
            if (m == 0) {
#pragma unroll
                for (int j = 0; j < 4; j++)
                    g_kT[(size_t)(b * HS + hg * 4 + j) * T + t] = vals[j];
            } else if (m == 1) {
#pragma unroll
                for (int j = 0; j < 4; j++)
                    g_qT[(size_t)(b * HS + hg * 4 + j) * T + t] = vals[j];
            } else {
                *(float4*)(g_v + (size_t)row * HS + hg * 4) =
                    make_float4(vals[0], vals[1], vals[2], vals[3]);
            }
        }
    }
}

// =====================================================================
// K2a: S = 8 * q k^T.  BM=128 t, BN=256 v, 256 threads, microtile 8t x 16v.
// j-major permuted smem layout -> conflict-free 16B-lane-stride LDS.
// =====================================================================
__global__ __launch_bounds__(256, 1) void qk_kernel()
{
    extern __shared__ float4 sm4[];
    float4* Q4 = sm4;             // [64 c][32 t4] perm: idx = (x&1)*16 + (x>>1)
    float4* K4 = sm4 + 64 * 32;   // [64 c][64 v4] perm: idx = (x&3)*16 + (x>>2)

    const int v0  = blockIdx.x * 256;
    const int t0  = blockIdx.y * 128;
    const int b   = blockIdx.z;
    const int tid = threadIdx.x;

    const float4* qT4 = (const float4*)g_qT;
    const float4* kT4 = (const float4*)g_kT;

#pragma unroll
    for (int it = 0; it < 8; it++) {
        int idx = tid + it * 256;            // 0..2047
        int c = idx >> 5, x4 = idx & 31;
        int perm = ((x4 & 1) << 4) | (x4 >> 1);
        Q4[c * 32 + perm] = qT4[(size_t)(b * HS + c) * (T / 4) + (t0 >> 2) + x4];
    }
#pragma unroll
    for (int it = 0; it < 16; it++) {
        int idx = tid + it * 256;            // 0..4095
        int c = idx >> 6, x4 = idx & 63;
        int perm = ((x4 & 3) << 4) | (x4 >> 2);
        K4[c * 64 + perm] = kT4[(size_t)(b * HS + c) * (T / 4) + (v0 >> 2) + x4];
    }
    __syncthreads();

    const int tg = tid >> 4;   // t = tg*8
    const int vg = tid & 15;   // v = vg*16

    ull acc[8][8];
#pragma unroll
    for (int i = 0; i < 8; i++)
#pragma unroll
        for (int p = 0; p < 8; p++) acc[i][p] = 0ull;

#pragma unroll 4
    for (int c = 0; c < 64; c++) {
        float4 qa = Q4[c * 32 + tg];          // t 8tg.. (even t4)
        float4 qb = Q4[c * 32 + 16 + tg];     // odd t4
        float4 k0 = K4[c * 64 + vg];
        float4 k1 = K4[c * 64 + 16 + vg];
        float4 k2 = K4[c * 64 + 32 + vg];
        float4 k3 = K4[c * 64 + 48 + vg];
        ull as[8] = {splat2(qa.x), splat2(qa.y), splat2(qa.z), splat2(qa.w),
                     splat2(qb.x), splat2(qb.y), splat2(qb.z), splat2(qb.w)};
        ull kp[8] = {pack2(k0.x, k0.y), pack2(k0.z, k0.w),
                     pack2(k1.x, k1.y), pack2(k1.z, k1.w),
                     pack2(k2.x, k2.y), pack2(k2.z, k2.w),
                     pack2(k3.x, k3.y), pack2(k3.z, k3.w)};
#pragma unroll
        for (int i = 0; i < 8; i++)
#pragma unroll
            for (int p = 0; p < 8; p++) ffma2(acc[i][p], as[i], kp[p]);
    }

#pragma unroll
    for (int i = 0; i < 8; i++) {
        int trow = t0 + tg * 8 + i;
        float* srow = g_s + ((size_t)(b * T + trow)) * T + v0 + vg * 16;
#pragma unroll
        for (int p = 0; p < 4; p++) {
            float2 e0 = unpack2(acc[i][2 * p]), e1 = unpack2(acc[i][2 * p + 1]);
            *(float4*)(srow + 4 * p) =
                make_float4(8.f * e0.x, 8.f * e0.y, 8.f * e1.x, 8.f * e1.y);
        }
    }
}

// =====================================================================
// K2b: S += q . rel.  grid t. 256 threads, thread = 1 v x 4 b-pairs.
// rel read ONCE via cp.async double-buffered 256-v tiles.
// =====================================================================
__global__ __launch_bounds__(256, 1) void rel_kernel(const float* __restrict__ rel)
{
    __shared__ float4 R4[2][256][16];                 // 128 KB, XOR-swizzled
    __shared__ __align__(16) ull qsP[4][64];          // [pair][c] 2 KB

    const int t   = blockIdx.x;
    const int tid = threadIdx.x;

    // stage q pairs: thread (pr = tid>>6, c = tid&63)
    {
        int pr = tid >> 6;
        int c  = tid & 63;
        float qa = g_qT[(size_t)((2 * pr + 0) * HS + c) * T + t];
        float qb = g_qT[(size_t)((2 * pr + 1) * HS + c) * T + t];
        qsP[pr][c] = pack2(qa, qb);
    }

    const int v  = tid;          // 0..255 within tile
    const int sw = tid & 15;

    const float4* relt = (const float4*)(rel + (size_t)t * T * HS);
    const size_t TT = (size_t)T * T;
    const size_t srow0 = (size_t)t * T;   // + b*TT

    // tile prefetch helper indices: thread stages 16 float4
    const int lvv = tid >> 4;    // base row 0..15 (+16 per it)
    const int lc4 = tid & 15;

    // prefetch tile 0
#pragma unroll
    for (int it = 0; it < 16; it++) {
        int vv = lvv + it * 16;
        cp_async16(&R4[0][vv][lc4 ^ (vv & 15)], &relt[(size_t)vv * 16 + lc4]);
    }
    cp_commit();

    const int NT = T / 256;   // 8 tiles
    for (int n = 0; n < NT; n++) {
        int buf = n & 1;
        if (n + 1 < NT) {
#pragma unroll
            for (int it = 0; it < 16; it++) {
                int vv = lvv + it * 16;
                cp_async16(&R4[buf ^ 1][vv][lc4 ^ (vv & 15)],
                           &relt[(size_t)((n + 1) * 256 + vv) * 16 + lc4]);
            }
            cp_commit();
            cp_wait<1>();
        } else {
            cp_wait<0>();
        }
        __syncthreads();

        // prefetch S values for RMW (8 rows: 4 pairs x 2 batches)
        size_t si = srow0 + n * 256 + v;
        float s[8];
#pragma unroll
        for (int bb = 0; bb < 8; bb++) s[bb] = g_s[si + (size_t)bb * TT];

        ull acc[4] = {0ull, 0ull, 0ull, 0ull};
#pragma unroll
        for (int c4 = 0; c4 < 16; c4++) {
            float4 r4 = R4[buf][v][c4 ^ sw];
            ull rx = splat2(r4.x), ry = splat2(r4.y), rz = splat2(r4.z), rw = splat2(r4.w);
#pragma unroll
            for (int pr = 0; pr < 4; pr++) {
                ulonglong2 qa = *(const ulonglong2*)&qsP[pr][c4 * 4];
                ulonglong2 qb = *(const ulonglong2*)&qsP[pr][c4 * 4 + 2];
                ffma2(acc[pr], qa.x, rx);
                ffma2(acc[pr], qa.y, ry);
                ffma2(acc[pr], qb.x, rz);
                ffma2(acc[pr], qb.y, rw);
            }
        }

#pragma unroll
        for (int pr = 0; pr < 4; pr++) {
            float2 f = unpack2(acc[pr]);
            g_s[si + (size_t)(2 * pr + 0) * TT] = s[2 * pr + 0] + f.x;
            g_s[si + (size_t)(2 * pr + 1) * TT] = s[2 * pr + 1] + f.y;
        }
        __syncthreads();   // protect buf before it is overwritten by prefetch n+2
    }
}

// =====================================================================
// K3: softmax + PV. 16 t rows / block, 512 threads / 16 warps, 2 CTAs/SM.
// att fp16 stride 24; PV acc packed over t (half2 -> float2 direct).
// =====================================================================
__global__ __launch_bounds__(512, 2) void soft_pv_kernel(float* __restrict__ out)
{
    extern __shared__ __align__(16) unsigned char smraw[];
    __half* attH = (__half*)smraw;          // [2048][24] fp16 = 96 KB
    float*  pout = (float*)smraw;           // reused after sync: [16][16][64] = 64 KB
    __shared__ float invl[16];

    const int t0   = blockIdx.x * 16;
    const int b    = blockIdx.y;
    const int tid  = threadIdx.x;
    const int w    = tid >> 5;      // 0..15
    const int lane = tid & 31;

    // softmax of row w (one warp per row)
    {
        const float4* srow4 = (const float4*)(g_s + ((size_t)(b * T + t0 + w)) * T);
        float m = -3.4e38f;
#pragma unroll
        for (int i = 0; i < 16; i++) {
            float4 sv = srow4[i * 32 + lane];
            m = fmaxf(m, fmaxf(fmaxf(sv.x, sv.y), fmaxf(sv.z, sv.w)));
        }
#pragma unroll
        for (int o = 16; o > 0; o >>= 1)
            m = fmaxf(m, __shfl_xor_sync(0xffffffffu, m, o));

        const float* srow = g_s + ((size_t)(b * T + t0 + w)) * T;
        float sum = 0.f;
#pragma unroll 8
        for (int i = 0; i < 64; i++) {
            int vi = i * 32 + lane;
            float e = __expf(srow[vi] - m);
            attH[vi * 24 + w] = __float2half_rn(e);
            sum += e;
        }
#pragma unroll
        for (int o = 16; o > 0; o >>= 1)
            sum += __shfl_xor_sync(0xffffffffu, sum, o);
        if (lane == 0) invl[w] = 1.f / sum;
    }
    __syncthreads();

    // PV: warp w handles v in [w*128, w*128+128)
    const int th = lane >> 4;    // t-half: rows th*8..th*8+7
    const int hg = lane & 15;    // h = hg*4..hg*4+3
    const float4* vb = (const float4*)(g_v + (size_t)b * T * HS) + hg;

    // acc[tp][h]: packed over (t = th*8+2tp, +1), h scalar
    ull acc[4][4];
#pragma unroll
    for (int tp = 0; tp < 4; tp++)
#pragma unroll
        for (int h = 0; h < 4; h++) acc[tp][h] = 0ull;

    const int vbeg = w * 128;
#pragma unroll 2
    for (int v = vbeg; v < vbeg + 128; v++) {
        float4 vv = vb[(size_t)v * 16];
        ull sv[4] = {splat2(vv.x), splat2(vv.y), splat2(vv.z), splat2(vv.w)};
        uint4 raw = *(const uint4*)(attH + v * 24 + th * 8);   // 8 halves = 4 half2
        const __half2* h2 = (const __half2*)&raw;
#pragma unroll
        for (int tp = 0; tp < 4; tp++) {
            float2 f = __half22float2(h2[tp]);
            ull ap = pack2(f.x, f.y);
#pragma unroll
            for (int h = 0; h < 4; h++) ffma2(acc[tp][h], ap, sv[h]);
        }
    }

    __syncthreads();   // all attH reads done before overwriting with partials

    float* pw = pout + w * 1024;
#pragma unroll
    for (int tp = 0; tp < 4; tp++) {
        int r0 = th * 8 + 2 * tp;
        float2 f0 = unpack2(acc[tp][0]), f1 = unpack2(acc[tp][1]);
        float2 f2 = unpack2(acc[tp][2]), f3 = unpack2(acc[tp][3]);
        *(float4*)(pw + r0 * 64 + hg * 4)       = make_float4(f0.x, f1.x, f2.x, f3.x);
        *(float4*)(pw + (r0 + 1) * 64 + hg * 4) = make_float4(f0.y, f1.y, f2.y, f3.y);
    }
    __syncthreads();

    // reduce 16 warps' partials
    {
        int tt = tid >> 5;            // 0..15
        int h2i = (tid & 31) * 2;     // 0..62 step 2
        float2 s = make_float2(0.f, 0.f);
#pragma unroll
        for (int ww = 0; ww < 16; ww++) {
            float2 p = *(float2*)(pout + ww * 1024 + tt * 64 + h2i);
            s.x += p.x; s.y += p.y;
        }
        float sc = invl[tt];
        *(float2*)(out + ((size_t)(b * T + t0 + tt)) * HS + h2i) =
            make_float2(s.x * sc, s.y * sc);
    }
}

// =====================================================================
extern "C" void kernel_launch(void* const* d_in, const int* in_sizes, int n_in,
                              void* d_out, int out_size)
{
    (void)in_sizes; (void)n_in; (void)out_size;
    const float* x   = (const float*)d_in[0];
    const float* Wk  = (const float*)d_in[1];
    const float* bk  = (const float*)d_in[2];
    const float* Wq  = (const float*)d_in[3];
    const float* bq  = (const float*)d_in[4];
    const float* Wv  = (const float*)d_in[5];
    const float* bv  = (const float*)d_in[6];
    const float* rel = (const float*)d_in[7];
    float* out = (float*)d_out;

    proj_kernel<<<(B * T) / 64, 256>>>(x, Wk, bk, Wq, bq, Wv, bv);

    const int qk_smem = (64 * 32 + 64 * 64) * sizeof(float4);   // 96 KB
    cudaFuncSetAttribute(qk_kernel, cudaFuncAttributeMaxDynamicSharedMemorySize, qk_smem);
    qk_kernel<<<dim3(T / 256, T / 128, B), 256, qk_smem>>>();

    rel_kernel<<<T, 256>>>(rel);

    const int k3_smem = 2048 * 24 * (int)sizeof(__half);  // 96 KB
    cudaFuncSetAttribute(soft_pv_kernel, cudaFuncAttributeMaxDynamicSharedMemorySize, k3_smem);
    soft_pv_kernel<<<dim3(T / 16, B), 512, k3_smem>>>(out);
}